// round 2
// baseline (speedup 1.0000x reference)
#include <cuda_runtime.h>
#include <math.h>

#define D_DIM 768
#define H_DIM 1536
#define E_NUM 8
#define TOPK  2
#define MAXTOK 32768
#define MAXSLOTS (MAXTOK * TOPK)

typedef unsigned long long ull;

// ---------------- device scratch (static, no runtime alloc) ----------------
__device__ int   g_cnt[E_NUM];
__device__ int   g_base[E_NUM];
__device__ int   g_fill[E_NUM];
__device__ int   g_te[MAXTOK * TOPK];
__device__ float g_tw[MAXTOK * TOPK];
__device__ int   g_tok[MAXSLOTS];
__device__ float g_w[MAXSLOTS];
__device__ float g_h[(size_t)MAXSLOTS * H_DIM];   // ~402 MB fp32 scratch

// ---------------- f32x2 packed helpers ----------------
__device__ __forceinline__ ull dup2(float x) {
    unsigned r = __float_as_uint(x);
    ull u;
    asm("mov.b64 %0, {%1, %1};" : "=l"(u) : "r"(r));
    return u;
}
__device__ __forceinline__ void fma2(ull& acc, ull a, ull b) {
    asm("fma.rn.f32x2 %0, %1, %2, %0;" : "+l"(acc) : "l"(a), "l"(b));
}
union F2U { ull u; float2 f; };

// ---------------- kernel 0: zero output ----------------
__global__ void zero_out_kernel(float4* out, int n4) {
    int i = blockIdx.x * blockDim.x + threadIdx.x;
    int stride = gridDim.x * blockDim.x;
    float4 z = make_float4(0.f, 0.f, 0.f, 0.f);
    for (; i < n4; i += stride) out[i] = z;
}
__global__ void zero_meta_kernel() {
    int t = threadIdx.x;
    if (t < E_NUM) { g_cnt[t] = 0; g_fill[t] = 0; }
}

// ---------------- kernel 1: routing (top-2 + softmax + histogram) ----------------
__global__ void route_kernel(const float* __restrict__ scores, int ntok) {
    int t = blockIdx.x * blockDim.x + threadIdx.x;
    if (t >= ntok) return;
    float s[E_NUM];
#pragma unroll
    for (int j = 0; j < E_NUM; ++j) s[j] = scores[t * E_NUM + j];
    int i0 = 0; float v0 = s[0];
#pragma unroll
    for (int j = 1; j < E_NUM; ++j) if (s[j] > v0) { v0 = s[j]; i0 = j; }
    int i1 = -1; float v1 = -INFINITY;
#pragma unroll
    for (int j = 0; j < E_NUM; ++j) if (j != i0 && s[j] > v1) { v1 = s[j]; i1 = j; }
    float e1 = expf(v1 - v0);
    float inv = 1.0f / (1.0f + e1);
    g_te[2 * t]     = i0;  g_tw[2 * t]     = inv;
    g_te[2 * t + 1] = i1;  g_tw[2 * t + 1] = e1 * inv;
    atomicAdd(&g_cnt[i0], 1);
    atomicAdd(&g_cnt[i1], 1);
}

// ---------------- kernel 2: 8-wide exclusive scan ----------------
__global__ void scan_kernel() {
    if (threadIdx.x == 0) {
        int b = 0;
        for (int e = 0; e < E_NUM; ++e) { g_base[e] = b; b += g_cnt[e]; }
    }
}

// ---------------- kernel 3: scatter tokens into expert slot lists ----------------
__global__ void scatter_kernel(int ntok) {
    int t = blockIdx.x * blockDim.x + threadIdx.x;
    if (t >= ntok) return;
#pragma unroll
    for (int k = 0; k < TOPK; ++k) {
        int e = g_te[2 * t + k];
        int pos = g_base[e] + atomicAdd(&g_fill[e], 1);
        g_tok[pos] = t;
        g_w[pos]   = g_tw[2 * t + k];
    }
}

// ---------------- pass 1: h = (X@W1) * sigmoid(X@Wg), grouped by expert ----------
// Tile: BM=64 tokens, BN=64 H-cols (both W1 and Wg), BK=16, 128 threads.
__global__ __launch_bounds__(128)
void pass1_kernel(const float* __restrict__ X,
                  const float* __restrict__ W1,
                  const float* __restrict__ Wg) {
    int e = blockIdx.z;
    int cnt = g_cnt[e];
    int m0 = blockIdx.y * 64;
    if (m0 >= cnt) return;
    int n0 = blockIdx.x * 64;
    int base = g_base[e];
    const float* W1e = W1 + (size_t)e * D_DIM * H_DIM;
    const float* Wge = Wg + (size_t)e * D_DIM * H_DIM;

    __shared__ __align__(16) float As[16][68];
    __shared__ __align__(16) float B1s[16][64];
    __shared__ __align__(16) float Bgs[16][64];
    __shared__ int s_tok[64];

    int tid = threadIdx.x;
    if (tid < 64) {
        int g = m0 + tid;
        s_tok[tid] = (g < cnt) ? g_tok[base + g] : -1;
    }
    __syncthreads();

    // loader mapping
    int lm = tid >> 1;           // 0..63 : token row in tile
    int lk = (tid & 1) << 3;     // 0 or 8
    int tokm = s_tok[lm];
    const float* xrow = (tokm >= 0) ? (X + (size_t)tokm * D_DIM) : 0;
    int br = tid >> 4;           // 0..7
    int bc = (tid & 15) << 2;    // 0..60

    // compute mapping
    int tx = tid & 15;           // cols tx*4 .. tx*4+3
    int ty = tid >> 4;           // rows ty*8 .. ty*8+7

    ull acc1[8][2], accg[8][2];
#pragma unroll
    for (int m = 0; m < 8; ++m) { acc1[m][0] = acc1[m][1] = 0ULL; accg[m][0] = accg[m][1] = 0ULL; }

    for (int kt = 0; kt < D_DIM; kt += 16) {
        float4 va0 = make_float4(0.f,0.f,0.f,0.f), va1 = va0;
        if (xrow) {
            va0 = *(const float4*)(xrow + kt + lk);
            va1 = *(const float4*)(xrow + kt + lk + 4);
        }
        float4 vb1a = *(const float4*)(W1e + (size_t)(kt + br) * H_DIM + n0 + bc);
        float4 vb1b = *(const float4*)(W1e + (size_t)(kt + br + 8) * H_DIM + n0 + bc);
        float4 vbga = *(const float4*)(Wge + (size_t)(kt + br) * H_DIM + n0 + bc);
        float4 vbgb = *(const float4*)(Wge + (size_t)(kt + br + 8) * H_DIM + n0 + bc);
        __syncthreads();
        As[lk + 0][lm] = va0.x; As[lk + 1][lm] = va0.y;
        As[lk + 2][lm] = va0.z; As[lk + 3][lm] = va0.w;
        As[lk + 4][lm] = va1.x; As[lk + 5][lm] = va1.y;
        As[lk + 6][lm] = va1.z; As[lk + 7][lm] = va1.w;
        *(float4*)&B1s[br][bc]     = vb1a;
        *(float4*)&B1s[br + 8][bc] = vb1b;
        *(float4*)&Bgs[br][bc]     = vbga;
        *(float4*)&Bgs[br + 8][bc] = vbgb;
        __syncthreads();
#pragma unroll
        for (int k = 0; k < 16; ++k) {
            float4 a0 = *(const float4*)&As[k][ty << 3];
            float4 a1 = *(const float4*)&As[k][(ty << 3) + 4];
            ulonglong2 b1 = *(const ulonglong2*)&B1s[k][tx << 2];
            ulonglong2 bg = *(const ulonglong2*)&Bgs[k][tx << 2];
            float am[8] = {a0.x, a0.y, a0.z, a0.w, a1.x, a1.y, a1.z, a1.w};
#pragma unroll
            for (int m = 0; m < 8; ++m) {
                ull ap = dup2(am[m]);
                fma2(acc1[m][0], ap, b1.x);
                fma2(acc1[m][1], ap, b1.y);
                fma2(accg[m][0], ap, bg.x);
                fma2(accg[m][1], ap, bg.y);
            }
        }
    }

    // epilogue: gate and store h
#pragma unroll
    for (int m = 0; m < 8; ++m) {
        int row = (ty << 3) + m;
        if (s_tok[row] < 0) continue;
        int gslot = base + m0 + row;
        F2U h0, h1, q0, q1;
        h0.u = acc1[m][0]; h1.u = acc1[m][1];
        q0.u = accg[m][0]; q1.u = accg[m][1];
        float4 o;
        o.x = h0.f.x * (1.f / (1.f + __expf(-q0.f.x)));
        o.y = h0.f.y * (1.f / (1.f + __expf(-q0.f.y)));
        o.z = h1.f.x * (1.f / (1.f + __expf(-q1.f.x)));
        o.w = h1.f.y * (1.f / (1.f + __expf(-q1.f.y)));
        *(float4*)&g_h[(size_t)gslot * H_DIM + n0 + (tx << 2)] = o;
    }
}

// ---------------- pass 2: out += w * (h @ W2), grouped by expert ----------------
// Tile: BM=64 slots, BN=128 D-cols, BK=16, 128 threads.
__global__ __launch_bounds__(128)
void pass2_kernel(const float* __restrict__ W2, float* __restrict__ out) {
    int e = blockIdx.z;
    int cnt = g_cnt[e];
    int m0 = blockIdx.y * 64;
    if (m0 >= cnt) return;
    int n0 = blockIdx.x * 128;
    int base = g_base[e];
    const float* W2e = W2 + (size_t)e * H_DIM * D_DIM;

    __shared__ __align__(16) float As[16][68];
    __shared__ __align__(16) float Bs[16][128];
    __shared__ int   s_tok[64];
    __shared__ float s_w[64];

    int tid = threadIdx.x;
    if (tid < 64) {
        int g = m0 + tid;
        if (g < cnt) { s_tok[tid] = g_tok[base + g]; s_w[tid] = g_w[base + g]; }
        else         { s_tok[tid] = -1;              s_w[tid] = 0.f; }
    }
    __syncthreads();

    int lm = tid >> 1;
    int lk = (tid & 1) << 3;
    bool avalid = (s_tok[lm] >= 0);
    const float* hrow = g_h + (size_t)(base + m0 + lm) * H_DIM;
    int br = tid >> 5;          // 0..3
    int bc = (tid & 31) << 2;   // 0..124

    int tx = tid & 15;          // cols tx*8 .. +7
    int ty = tid >> 4;          // rows ty*8 .. +7

    ull acc[8][4];
#pragma unroll
    for (int m = 0; m < 8; ++m)
#pragma unroll
        for (int j = 0; j < 4; ++j) acc[m][j] = 0ULL;

    for (int kt = 0; kt < H_DIM; kt += 16) {
        float4 va0 = make_float4(0.f,0.f,0.f,0.f), va1 = va0;
        if (avalid) {
            va0 = *(const float4*)(hrow + kt + lk);
            va1 = *(const float4*)(hrow + kt + lk + 4);
        }
        float4 vb[4];
#pragma unroll
        for (int i = 0; i < 4; ++i)
            vb[i] = *(const float4*)(W2e + (size_t)(kt + br + (i << 2)) * D_DIM + n0 + bc);
        __syncthreads();
        As[lk + 0][lm] = va0.x; As[lk + 1][lm] = va0.y;
        As[lk + 2][lm] = va0.z; As[lk + 3][lm] = va0.w;
        As[lk + 4][lm] = va1.x; As[lk + 5][lm] = va1.y;
        As[lk + 6][lm] = va1.z; As[lk + 7][lm] = va1.w;
#pragma unroll
        for (int i = 0; i < 4; ++i)
            *(float4*)&Bs[br + (i << 2)][bc] = vb[i];
        __syncthreads();
#pragma unroll
        for (int k = 0; k < 16; ++k) {
            float4 a0 = *(const float4*)&As[k][ty << 3];
            float4 a1 = *(const float4*)&As[k][(ty << 3) + 4];
            ulonglong2 b0 = *(const ulonglong2*)&Bs[k][tx << 3];
            ulonglong2 b1 = *(const ulonglong2*)&Bs[k][(tx << 3) + 4];
            float am[8] = {a0.x, a0.y, a0.z, a0.w, a1.x, a1.y, a1.z, a1.w};
#pragma unroll
            for (int m = 0; m < 8; ++m) {
                ull ap = dup2(am[m]);
                fma2(acc[m][0], ap, b0.x);
                fma2(acc[m][1], ap, b0.y);
                fma2(acc[m][2], ap, b1.x);
                fma2(acc[m][3], ap, b1.y);
            }
        }
    }

    // epilogue: scaled scatter-add into out
#pragma unroll
    for (int m = 0; m < 8; ++m) {
        int row = (ty << 3) + m;
        int tok = s_tok[row];
        if (tok < 0) continue;
        float w = s_w[row];
        float* op = out + (size_t)tok * D_DIM + n0 + (tx << 3);
        F2U u0, u1, u2, u3;
        u0.u = acc[m][0]; u1.u = acc[m][1]; u2.u = acc[m][2]; u3.u = acc[m][3];
        atomicAdd(op + 0, w * u0.f.x); atomicAdd(op + 1, w * u0.f.y);
        atomicAdd(op + 2, w * u1.f.x); atomicAdd(op + 3, w * u1.f.y);
        atomicAdd(op + 4, w * u2.f.x); atomicAdd(op + 5, w * u2.f.y);
        atomicAdd(op + 6, w * u3.f.x); atomicAdd(op + 7, w * u3.f.y);
    }
}

// ---------------- launch ----------------
extern "C" void kernel_launch(void* const* d_in, const int* in_sizes, int n_in,
                              void* d_out, int out_size) {
    const float* X      = (const float*)d_in[0];
    const float* scores = (const float*)d_in[1];
    const float* W1     = (const float*)d_in[2];
    const float* Wg     = (const float*)d_in[3];
    const float* W2     = (const float*)d_in[4];
    float* out = (float*)d_out;

    int ntok = in_sizes[0] / D_DIM;   // 32768
    int n4 = out_size / 4;

    zero_out_kernel<<<2048, 256>>>((float4*)out, n4);
    zero_meta_kernel<<<1, 32>>>();
    route_kernel<<<(ntok + 255) / 256, 256>>>(scores, ntok);
    scan_kernel<<<1, 32>>>();
    scatter_kernel<<<(ntok + 255) / 256, 256>>>(ntok);

    dim3 g1(H_DIM / 64, (ntok + 63) / 64, E_NUM);
    pass1_kernel<<<g1, 128>>>(X, W1, Wg);

    dim3 g2(D_DIM / 128, (ntok + 63) / 64, E_NUM);
    pass2_kernel<<<g2, 128>>>(W2, out);
}

// round 3
// speedup vs baseline: 1.0019x; 1.0019x over previous
#include <cuda_runtime.h>
#include <math.h>

#define D_DIM 768
#define H_DIM 1536
#define E_NUM 8
#define TOPK  2
#define MAXTOK 32768
#define MAXSLOTS (MAXTOK * TOPK)

typedef unsigned long long ull;

// ---------------- device scratch (static, no runtime alloc) ----------------
__device__ int   g_cnt[E_NUM];
__device__ int   g_base[E_NUM];
__device__ int   g_fill[E_NUM];
__device__ int   g_te[MAXTOK * TOPK];
__device__ float g_tw[MAXTOK * TOPK];
__device__ int   g_tok[MAXSLOTS];
__device__ float g_w[MAXSLOTS];
__device__ float g_h[(size_t)MAXSLOTS * H_DIM];   // ~402 MB fp32 scratch

// ---------------- f32x2 packed helpers ----------------
__device__ __forceinline__ ull dup2(float x) {
    unsigned r = __float_as_uint(x);
    ull u;
    asm("mov.b64 %0, {%1, %1};" : "=l"(u) : "r"(r));
    return u;
}
__device__ __forceinline__ void fma2(ull& acc, ull a, ull b) {
    asm("fma.rn.f32x2 %0, %1, %2, %0;" : "+l"(acc) : "l"(a), "l"(b));
}
union F2U { ull u; float2 f; };

// ---------------- kernel 0: zero output ----------------
__global__ void zero_out_kernel(float4* out, int n4) {
    int i = blockIdx.x * blockDim.x + threadIdx.x;
    int stride = gridDim.x * blockDim.x;
    float4 z = make_float4(0.f, 0.f, 0.f, 0.f);
    for (; i < n4; i += stride) out[i] = z;
}
__global__ void zero_meta_kernel() {
    int t = threadIdx.x;
    if (t < E_NUM) { g_cnt[t] = 0; g_fill[t] = 0; }
}

// ---------------- kernel 1: routing (top-2 + softmax + histogram) ----------------
__global__ void route_kernel(const float* __restrict__ scores, int ntok) {
    int t = blockIdx.x * blockDim.x + threadIdx.x;
    if (t >= ntok) return;
    float s[E_NUM];
#pragma unroll
    for (int j = 0; j < E_NUM; ++j) s[j] = scores[t * E_NUM + j];
    int i0 = 0; float v0 = s[0];
#pragma unroll
    for (int j = 1; j < E_NUM; ++j) if (s[j] > v0) { v0 = s[j]; i0 = j; }
    int i1 = -1; float v1 = -INFINITY;
#pragma unroll
    for (int j = 0; j < E_NUM; ++j) if (j != i0 && s[j] > v1) { v1 = s[j]; i1 = j; }
    float e1 = expf(v1 - v0);
    float inv = 1.0f / (1.0f + e1);
    g_te[2 * t]     = i0;  g_tw[2 * t]     = inv;
    g_te[2 * t + 1] = i1;  g_tw[2 * t + 1] = e1 * inv;
    atomicAdd(&g_cnt[i0], 1);
    atomicAdd(&g_cnt[i1], 1);
}

// ---------------- kernel 2: 8-wide exclusive scan ----------------
__global__ void scan_kernel() {
    if (threadIdx.x == 0) {
        int b = 0;
        for (int e = 0; e < E_NUM; ++e) { g_base[e] = b; b += g_cnt[e]; }
    }
}

// ---------------- kernel 3: scatter tokens into expert slot lists ----------------
__global__ void scatter_kernel(int ntok) {
    int t = blockIdx.x * blockDim.x + threadIdx.x;
    if (t >= ntok) return;
#pragma unroll
    for (int k = 0; k < TOPK; ++k) {
        int e = g_te[2 * t + k];
        int pos = g_base[e] + atomicAdd(&g_fill[e], 1);
        g_tok[pos] = t;
        g_w[pos]   = g_tw[2 * t + k];
    }
}

// ---------------- pass 1: h = (X@W1) * sigmoid(X@Wg), grouped by expert ----------
// Tile: BM=64 tokens, BN=64 H-cols (both W1 and Wg), BK=16, 128 threads.
__global__ __launch_bounds__(128)
void pass1_kernel(const float* __restrict__ X,
                  const float* __restrict__ W1,
                  const float* __restrict__ Wg) {
    int e = blockIdx.z;
    int cnt = g_cnt[e];
    int m0 = blockIdx.y * 64;
    if (m0 >= cnt) return;
    int n0 = blockIdx.x * 64;
    int base = g_base[e];
    const float* W1e = W1 + (size_t)e * D_DIM * H_DIM;
    const float* Wge = Wg + (size_t)e * D_DIM * H_DIM;

    __shared__ __align__(16) float As[16][68];
    __shared__ __align__(16) float B1s[16][64];
    __shared__ __align__(16) float Bgs[16][64];
    __shared__ int s_tok[64];

    int tid = threadIdx.x;
    if (tid < 64) {
        int g = m0 + tid;
        s_tok[tid] = (g < cnt) ? g_tok[base + g] : -1;
    }
    __syncthreads();

    // loader mapping
    int lm = tid >> 1;           // 0..63 : token row in tile
    int lk = (tid & 1) << 3;     // 0 or 8
    int tokm = s_tok[lm];
    const float* xrow = (tokm >= 0) ? (X + (size_t)tokm * D_DIM) : 0;
    int br = tid >> 4;           // 0..7
    int bc = (tid & 15) << 2;    // 0..60

    // compute mapping
    int tx = tid & 15;           // cols tx*4 .. tx*4+3
    int ty = tid >> 4;           // rows ty*8 .. ty*8+7

    ull acc1[8][2], accg[8][2];
#pragma unroll
    for (int m = 0; m < 8; ++m) { acc1[m][0] = acc1[m][1] = 0ULL; accg[m][0] = accg[m][1] = 0ULL; }

    for (int kt = 0; kt < D_DIM; kt += 16) {
        float4 va0 = make_float4(0.f,0.f,0.f,0.f), va1 = va0;
        if (xrow) {
            va0 = *(const float4*)(xrow + kt + lk);
            va1 = *(const float4*)(xrow + kt + lk + 4);
        }
        float4 vb1a = *(const float4*)(W1e + (size_t)(kt + br) * H_DIM + n0 + bc);
        float4 vb1b = *(const float4*)(W1e + (size_t)(kt + br + 8) * H_DIM + n0 + bc);
        float4 vbga = *(const float4*)(Wge + (size_t)(kt + br) * H_DIM + n0 + bc);
        float4 vbgb = *(const float4*)(Wge + (size_t)(kt + br + 8) * H_DIM + n0 + bc);
        __syncthreads();
        As[lk + 0][lm] = va0.x; As[lk + 1][lm] = va0.y;
        As[lk + 2][lm] = va0.z; As[lk + 3][lm] = va0.w;
        As[lk + 4][lm] = va1.x; As[lk + 5][lm] = va1.y;
        As[lk + 6][lm] = va1.z; As[lk + 7][lm] = va1.w;
        *(float4*)&B1s[br][bc]     = vb1a;
        *(float4*)&B1s[br + 8][bc] = vb1b;
        *(float4*)&Bgs[br][bc]     = vbga;
        *(float4*)&Bgs[br + 8][bc] = vbgb;
        __syncthreads();
#pragma unroll
        for (int k = 0; k < 16; ++k) {
            float4 a0 = *(const float4*)&As[k][ty << 3];
            float4 a1 = *(const float4*)&As[k][(ty << 3) + 4];
            ulonglong2 b1 = *(const ulonglong2*)&B1s[k][tx << 2];
            ulonglong2 bg = *(const ulonglong2*)&Bgs[k][tx << 2];
            float am[8] = {a0.x, a0.y, a0.z, a0.w, a1.x, a1.y, a1.z, a1.w};
#pragma unroll
            for (int m = 0; m < 8; ++m) {
                ull ap = dup2(am[m]);
                fma2(acc1[m][0], ap, b1.x);
                fma2(acc1[m][1], ap, b1.y);
                fma2(accg[m][0], ap, bg.x);
                fma2(accg[m][1], ap, bg.y);
            }
        }
    }

    // epilogue: gate and store h
#pragma unroll
    for (int m = 0; m < 8; ++m) {
        int row = (ty << 3) + m;
        if (s_tok[row] < 0) continue;
        int gslot = base + m0 + row;
        F2U h0, h1, q0, q1;
        h0.u = acc1[m][0]; h1.u = acc1[m][1];
        q0.u = accg[m][0]; q1.u = accg[m][1];
        float4 o;
        o.x = h0.f.x * (1.f / (1.f + __expf(-q0.f.x)));
        o.y = h0.f.y * (1.f / (1.f + __expf(-q0.f.y)));
        o.z = h1.f.x * (1.f / (1.f + __expf(-q1.f.x)));
        o.w = h1.f.y * (1.f / (1.f + __expf(-q1.f.y)));
        *(float4*)&g_h[(size_t)gslot * H_DIM + n0 + (tx << 2)] = o;
    }
}

// ---------------- pass 2: out += w * (h @ W2), grouped by expert ----------------
// Tile: BM=64 slots, BN=128 D-cols, BK=16, 128 threads.
__global__ __launch_bounds__(128)
void pass2_kernel(const float* __restrict__ W2, float* __restrict__ out) {
    int e = blockIdx.z;
    int cnt = g_cnt[e];
    int m0 = blockIdx.y * 64;
    if (m0 >= cnt) return;
    int n0 = blockIdx.x * 128;
    int base = g_base[e];
    const float* W2e = W2 + (size_t)e * H_DIM * D_DIM;

    __shared__ __align__(16) float As[16][68];
    __shared__ __align__(16) float Bs[16][128];
    __shared__ int   s_tok[64];
    __shared__ float s_w[64];

    int tid = threadIdx.x;
    if (tid < 64) {
        int g = m0 + tid;
        if (g < cnt) { s_tok[tid] = g_tok[base + g]; s_w[tid] = g_w[base + g]; }
        else         { s_tok[tid] = -1;              s_w[tid] = 0.f; }
    }
    __syncthreads();

    int lm = tid >> 1;
    int lk = (tid & 1) << 3;
    bool avalid = (s_tok[lm] >= 0);
    const float* hrow = g_h + (size_t)(base + m0 + lm) * H_DIM;
    int br = tid >> 5;          // 0..3
    int bc = (tid & 31) << 2;   // 0..124

    int tx = tid & 15;          // cols tx*8 .. +7
    int ty = tid >> 4;          // rows ty*8 .. +7

    ull acc[8][4];
#pragma unroll
    for (int m = 0; m < 8; ++m)
#pragma unroll
        for (int j = 0; j < 4; ++j) acc[m][j] = 0ULL;

    for (int kt = 0; kt < H_DIM; kt += 16) {
        float4 va0 = make_float4(0.f,0.f,0.f,0.f), va1 = va0;
        if (avalid) {
            va0 = *(const float4*)(hrow + kt + lk);
            va1 = *(const float4*)(hrow + kt + lk + 4);
        }
        float4 vb[4];
#pragma unroll
        for (int i = 0; i < 4; ++i)
            vb[i] = *(const float4*)(W2e + (size_t)(kt + br + (i << 2)) * D_DIM + n0 + bc);
        __syncthreads();
        As[lk + 0][lm] = va0.x; As[lk + 1][lm] = va0.y;
        As[lk + 2][lm] = va0.z; As[lk + 3][lm] = va0.w;
        As[lk + 4][lm] = va1.x; As[lk + 5][lm] = va1.y;
        As[lk + 6][lm] = va1.z; As[lk + 7][lm] = va1.w;
#pragma unroll
        for (int i = 0; i < 4; ++i)
            *(float4*)&Bs[br + (i << 2)][bc] = vb[i];
        __syncthreads();
#pragma unroll
        for (int k = 0; k < 16; ++k) {
            float4 a0 = *(const float4*)&As[k][ty << 3];
            float4 a1 = *(const float4*)&As[k][(ty << 3) + 4];
            ulonglong2 b0 = *(const ulonglong2*)&Bs[k][tx << 3];
            ulonglong2 b1 = *(const ulonglong2*)&Bs[k][(tx << 3) + 4];
            float am[8] = {a0.x, a0.y, a0.z, a0.w, a1.x, a1.y, a1.z, a1.w};
#pragma unroll
            for (int m = 0; m < 8; ++m) {
                ull ap = dup2(am[m]);
                fma2(acc[m][0], ap, b0.x);
                fma2(acc[m][1], ap, b0.y);
                fma2(acc[m][2], ap, b1.x);
                fma2(acc[m][3], ap, b1.y);
            }
        }
    }

    // epilogue: scaled scatter-add into out
#pragma unroll
    for (int m = 0; m < 8; ++m) {
        int row = (ty << 3) + m;
        int tok = s_tok[row];
        if (tok < 0) continue;
        float w = s_w[row];
        float* op = out + (size_t)tok * D_DIM + n0 + (tx << 3);
        F2U u0, u1, u2, u3;
        u0.u = acc[m][0]; u1.u = acc[m][1]; u2.u = acc[m][2]; u3.u = acc[m][3];
        atomicAdd(op + 0, w * u0.f.x); atomicAdd(op + 1, w * u0.f.y);
        atomicAdd(op + 2, w * u1.f.x); atomicAdd(op + 3, w * u1.f.y);
        atomicAdd(op + 4, w * u2.f.x); atomicAdd(op + 5, w * u2.f.y);
        atomicAdd(op + 6, w * u3.f.x); atomicAdd(op + 7, w * u3.f.y);
    }
}

// ---------------- launch ----------------
extern "C" void kernel_launch(void* const* d_in, const int* in_sizes, int n_in,
                              void* d_out, int out_size) {
    const float* X      = (const float*)d_in[0];
    const float* scores = (const float*)d_in[1];
    const float* W1     = (const float*)d_in[2];
    const float* Wg     = (const float*)d_in[3];
    const float* W2     = (const float*)d_in[4];
    float* out = (float*)d_out;

    int ntok = in_sizes[0] / D_DIM;   // 32768
    int n4 = out_size / 4;

    zero_out_kernel<<<2048, 256>>>((float4*)out, n4);
    zero_meta_kernel<<<1, 32>>>();
    route_kernel<<<(ntok + 255) / 256, 256>>>(scores, ntok);
    scan_kernel<<<1, 32>>>();
    scatter_kernel<<<(ntok + 255) / 256, 256>>>(ntok);

    dim3 g1(H_DIM / 64, (ntok + 63) / 64, E_NUM);
    pass1_kernel<<<g1, 128>>>(X, W1, Wg);

    dim3 g2(D_DIM / 128, (ntok + 63) / 64, E_NUM);
    pass2_kernel<<<g2, 128>>>(W2, out);
}

// round 5
// speedup vs baseline: 2.6552x; 2.6502x over previous
#include <cuda_runtime.h>
#include <cuda_bf16.h>
#include <math.h>

typedef unsigned int u32;
typedef unsigned long long u64;

#define D_DIM 768
#define H_DIM 1536
#define E_NUM 8
#define MAXTILES 520
#define PS_MAX (MAXTILES * 128)
#define STAGE_BYTES 32768
#define SMEM_DYN (3 * STAGE_BYTES)

// ---------------- device scratch ----------------
__device__ int   g_cnt[E_NUM];
__device__ int   g_fill[E_NUM];
__device__ int   g_basep[E_NUM];
__device__ int   g_ntiles;
__device__ int   g_tile_e[MAXTILES];
__device__ int   g_te[PS_MAX];
__device__ float g_tw[PS_MAX];
__device__ int   g_pos[PS_MAX];
__device__ int   g_tok[PS_MAX];

// fragment-order operand images
// A (X gathered):  [tile][ks=48][mt=8][lane=32] uint4   (a0..a3 packed bf16x2)
__device__ __align__(128) uint4 g_aFh[(size_t)MAXTILES * 48 * 8 * 32];
__device__ __align__(128) uint4 g_aFl[(size_t)MAXTILES * 48 * 8 * 32];
// h (pass1 out):   [tile][ks=96][mt=8][lane=32] uint4
__device__ __align__(128) uint4 g_hFh[(size_t)MAXTILES * 96 * 8 * 32];
__device__ __align__(128) uint4 g_hFl[(size_t)MAXTILES * 96 * 8 * 32];
// B weights: [e][ks][ngrp][lane][4 tiles] uint2 (b0,b1)
__device__ __align__(128) uint2 g_w1Fh[(size_t)E_NUM * 48 * 48 * 32 * 4];
__device__ __align__(128) uint2 g_w1Fl[(size_t)E_NUM * 48 * 48 * 32 * 4];
__device__ __align__(128) uint2 g_wgFh[(size_t)E_NUM * 48 * 48 * 32 * 4];
__device__ __align__(128) uint2 g_wgFl[(size_t)E_NUM * 48 * 48 * 32 * 4];
__device__ __align__(128) uint2 g_w2Fh[(size_t)E_NUM * 96 * 24 * 32 * 4];
__device__ __align__(128) uint2 g_w2Fl[(size_t)E_NUM * 96 * 24 * 32 * 4];
__device__ __align__(128) float g_y[(size_t)PS_MAX * D_DIM];

// ---------------- helpers ----------------
__device__ __forceinline__ u32 smem_u32(const void* p) {
    u32 a;
    asm("{ .reg .u64 t; cvta.to.shared.u64 t, %1; cvt.u32.u64 %0, t; }" : "=r"(a) : "l"(p));
    return a;
}
__device__ __forceinline__ void cp16(u32 dst, const void* src) {
    asm volatile("cp.async.cg.shared.global [%0], [%1], 16;" :: "r"(dst), "l"(src));
}
#define CP_COMMIT() asm volatile("cp.async.commit_group;")
#define CP_WAIT1()  asm volatile("cp.async.wait_group 1;")

__device__ __forceinline__ void mma16816(float* c, u32 a0, u32 a1, u32 a2, u32 a3,
                                         u32 b0, u32 b1) {
    asm volatile(
        "mma.sync.aligned.m16n8k16.row.col.f32.bf16.bf16.f32 "
        "{%0,%1,%2,%3},{%4,%5,%6,%7},{%8,%9},{%0,%1,%2,%3};"
        : "+f"(c[0]), "+f"(c[1]), "+f"(c[2]), "+f"(c[3])
        : "r"(a0), "r"(a1), "r"(a2), "r"(a3), "r"(b0), "r"(b1));
}
__device__ __forceinline__ u32 pck(float x, float y) {
    __nv_bfloat162 v = __floats2bfloat162_rn(x, y);
    return *(u32*)&v;
}
__device__ __forceinline__ void split2(float x0, float x1, u32& hi, u32& lo) {
    __nv_bfloat16 h0 = __float2bfloat16(x0), h1 = __float2bfloat16(x1);
    float r0 = x0 - __bfloat162float(h0), r1 = x1 - __bfloat162float(h1);
    __nv_bfloat162 hv; hv.x = h0; hv.y = h1;
    hi = *(u32*)&hv;
    lo = pck(r0, r1);
}

// ---------------- routing ----------------
__global__ void zero_meta_kernel() {
    int t = threadIdx.x;
    if (t < E_NUM) { g_cnt[t] = 0; g_fill[t] = 0; }
}
__global__ void fill_tok_kernel() {
    int i = blockIdx.x * blockDim.x + threadIdx.x;
    if (i < PS_MAX) g_tok[i] = -1;
}
__global__ void route_kernel(const float* __restrict__ scores, int ntok) {
    int t = blockIdx.x * blockDim.x + threadIdx.x;
    if (t >= ntok) return;
    float s[E_NUM];
#pragma unroll
    for (int j = 0; j < E_NUM; ++j) s[j] = scores[t * E_NUM + j];
    int i0 = 0; float v0 = s[0];
#pragma unroll
    for (int j = 1; j < E_NUM; ++j) if (s[j] > v0) { v0 = s[j]; i0 = j; }
    int i1 = -1; float v1 = -INFINITY;
#pragma unroll
    for (int j = 0; j < E_NUM; ++j) if (j != i0 && s[j] > v1) { v1 = s[j]; i1 = j; }
    float e1 = expf(v1 - v0);
    float inv = 1.0f / (1.0f + e1);
    g_te[2*t] = i0;   g_tw[2*t] = inv;
    g_te[2*t+1] = i1; g_tw[2*t+1] = e1 * inv;
    atomicAdd(&g_cnt[i0], 1);
    atomicAdd(&g_cnt[i1], 1);
}
__global__ void scan_kernel() {
    if (threadIdx.x == 0) {
        int t = 0;
        for (int e = 0; e < E_NUM; ++e) {
            g_basep[e] = t * 128;
            int nt = (g_cnt[e] + 127) >> 7;
            for (int i = 0; i < nt; ++i) g_tile_e[t++] = e;
        }
        g_ntiles = t;
    }
}
__global__ void scatter_kernel(int ntok) {
    int t = blockIdx.x * blockDim.x + threadIdx.x;
    if (t >= ntok) return;
#pragma unroll
    for (int k = 0; k < 2; ++k) {
        int e = g_te[2*t + k];
        int pos = g_basep[e] + atomicAdd(&g_fill[e], 1);
        g_tok[pos] = t;
        g_pos[2*t + k] = pos;
    }
}

// ---------------- A gather -> fragment images ----------------
__global__ void __launch_bounds__(256) gather_a_kernel(const float* __restrict__ X) {
    int tile = blockIdx.x;
    if (tile >= g_ntiles) return;
    int tid = threadIdx.x;
    int mt = tid >> 5, lane = tid & 31;
    int r0 = mt * 16 + (lane >> 2);
    int r1 = r0 + 8;
    int k0 = (lane & 3) * 2;
    int tok0 = g_tok[tile * 128 + r0];
    int tok1 = g_tok[tile * 128 + r1];
    const float* x0 = (tok0 >= 0) ? X + (size_t)tok0 * D_DIM : 0;
    const float* x1 = (tok1 >= 0) ? X + (size_t)tok1 * D_DIM : 0;
    size_t ob = (size_t)tile * (48 * 8 * 32) + (size_t)mt * 32 + lane;
#pragma unroll 4
    for (int ks = 0; ks < 48; ++ks) {
        int kb = ks * 16 + k0;
        float2 f0a = x0 ? *(const float2*)(x0 + kb)     : make_float2(0.f, 0.f);
        float2 f0b = x0 ? *(const float2*)(x0 + kb + 8) : make_float2(0.f, 0.f);
        float2 f1a = x1 ? *(const float2*)(x1 + kb)     : make_float2(0.f, 0.f);
        float2 f1b = x1 ? *(const float2*)(x1 + kb + 8) : make_float2(0.f, 0.f);
        uint4 hi, lo;
        split2(f0a.x, f0a.y, hi.x, lo.x);
        split2(f1a.x, f1a.y, hi.y, lo.y);
        split2(f0b.x, f0b.y, hi.z, lo.z);
        split2(f1b.x, f1b.y, hi.w, lo.w);
        g_aFh[ob + (size_t)ks * 256] = hi;
        g_aFl[ob + (size_t)ks * 256] = lo;
    }
}

// ---------------- weight convert -> fragment images ----------------
// src [E][K][N] fp32 -> [e][ks][ngrp][lane][ti] uint2 hi/lo
__global__ void __launch_bounds__(256) conv_w_kernel(const float* __restrict__ src,
                                                     int which, int K, int N) {
    uint2 *dh, *dl;
    if (which == 0)      { dh = g_w1Fh; dl = g_w1Fl; }
    else if (which == 1) { dh = g_wgFh; dl = g_wgFl; }
    else                 { dh = g_w2Fh; dl = g_w2Fl; }
    int ks = blockIdx.x, nb = blockIdx.y, e = blockIdx.z;
    int NG = N / 32;
    __shared__ float sb[16][129];
    const float* s = src + (size_t)e * K * N + (size_t)ks * 16 * N + (size_t)nb * 128;
    int tid = threadIdx.x;
#pragma unroll
    for (int r = 0; r < 2; ++r) {
        int idx = tid + r * 256;          // 512 float4
        int row = idx >> 5, c4 = idx & 31;
        float4 v = *(const float4*)(s + (size_t)row * N + c4 * 4);
        sb[row][c4*4+0] = v.x; sb[row][c4*4+1] = v.y;
        sb[row][c4*4+2] = v.z; sb[row][c4*4+3] = v.w;
    }
    __syncthreads();
    size_t eb = (size_t)e * (size_t)(K / 16) * NG * 32 * 4;
#pragma unroll
    for (int r = 0; r < 2; ++r) {
        int slot = tid + r * 256;         // 512 = 16 ntiles x 32 lanes
        int nt = slot >> 5, lane = slot & 31;
        int n = nt * 8 + (lane >> 2);
        int kk = (lane & 3) * 2;
        u32 b0h, b0l, b1h, b1l;
        split2(sb[kk][n],     sb[kk+1][n], b0h, b0l);
        split2(sb[kk+8][n],   sb[kk+9][n], b1h, b1l);
        int ng = nb * 4 + (nt >> 2);
        int ti = nt & 3;
        size_t off = eb + (((size_t)ks * NG + ng) * 32 + lane) * 4 + ti;
        dh[off] = make_uint2(b0h, b1h);
        dl[off] = make_uint2(b0l, b1l);
    }
}

// ---------------- pass 1: h = (X@W1)*sigmoid(X@Wg) ----------------
// CTA: 256 thr = 8 warps (4M x 2N). M=128, N=64 per output. K chunk 32, 24 chunks.
__global__ void __launch_bounds__(256) pass1_mma(void) {
    int tile = blockIdx.y;
    if (tile >= g_ntiles) return;
    int nch = blockIdx.x;                  // 0..23 (64 H-cols each)
    int e = g_tile_e[tile];
    extern __shared__ char dsm[];
    u32 sbase = smem_u32(dsm);

    int tid = threadIdx.x;
    int wid = tid >> 5, lane = tid & 31;
    int wm = wid >> 1, wn = wid & 1;

    const uint4* Ah = g_aFh + (size_t)tile * (48 * 8 * 32);
    const uint4* Al = g_aFl + (size_t)tile * (48 * 8 * 32);
    size_t eb = (size_t)e * (48 * 48 * 32 * 4);
    const uint2* B1h = g_w1Fh + eb;
    const uint2* B1l = g_w1Fl + eb;
    const uint2* Bgh = g_wgFh + eb;
    const uint2* Bgl = g_wgFl + eb;

    // cp.async mapping precompute
    int ksl_b = tid >> 7;
    int ngl_b = (tid >> 6) & 1;
    int lane_b = (tid & 63) >> 1;
    int half_b = tid & 1;
    int ng = nch * 2 + ngl_b;

    auto issue = [&](int c, int slot) {
        u32 st = sbase + slot * STAGE_BYTES;
        const uint4* ah = Ah + (size_t)c * 512;
        const uint4* al = Al + (size_t)c * 512;
        cp16(st + tid * 16,                 ah + tid);
        cp16(st + (tid + 256) * 16,         ah + tid + 256);
        cp16(st + 8192 + tid * 16,          al + tid);
        cp16(st + 8192 + (tid + 256) * 16,  al + tid + 256);
        size_t bsrc = (((size_t)(2 * c + ksl_b) * 48 + ng) * 32 + lane_b) * 4 + half_b * 2;
        u32 bdst = ((ksl_b * 2 + ngl_b) * 32 + lane_b) * 32 + half_b * 16;
        cp16(st + 16384 + bdst, B1h + bsrc);
        cp16(st + 20480 + bdst, B1l + bsrc);
        cp16(st + 24576 + bdst, Bgh + bsrc);
        cp16(st + 28672 + bdst, Bgl + bsrc);
    };

    float acc1[2][4][4], accg[2][4][4];
#pragma unroll
    for (int i = 0; i < 2; ++i)
#pragma unroll
        for (int j = 0; j < 4; ++j)
#pragma unroll
            for (int k = 0; k < 4; ++k) { acc1[i][j][k] = 0.f; accg[i][j][k] = 0.f; }

    issue(0, 0); CP_COMMIT();
    issue(1, 1); CP_COMMIT();

    const int NCH_CHUNKS = 24;
    for (int c = 0; c < NCH_CHUNKS; ++c) {
        CP_WAIT1();
        __syncthreads();
        int slot = c % 3;
        const char* st = dsm + slot * STAGE_BYTES;
#pragma unroll
        for (int ksl = 0; ksl < 2; ++ksl) {
            uint4 ahf[2], alf[2];
#pragma unroll
            for (int i = 0; i < 2; ++i) {
                int mt = wm * 2 + i;
                u32 ao = ((ksl * 8 + mt) * 32 + lane) * 16;
                ahf[i] = *(const uint4*)(st + ao);
                alf[i] = *(const uint4*)(st + 8192 + ao);
            }
            u32 bo = ((ksl * 2 + wn) * 32 + lane) * 32;
            uint4 b1hA = *(const uint4*)(st + 16384 + bo);
            uint4 b1hB = *(const uint4*)(st + 16384 + bo + 16);
            uint4 b1lA = *(const uint4*)(st + 20480 + bo);
            uint4 b1lB = *(const uint4*)(st + 20480 + bo + 16);
            uint4 bghA = *(const uint4*)(st + 24576 + bo);
            uint4 bghB = *(const uint4*)(st + 24576 + bo + 16);
            uint4 bglA = *(const uint4*)(st + 28672 + bo);
            uint4 bglB = *(const uint4*)(st + 28672 + bo + 16);
            u32 b1h[4][2] = {{b1hA.x,b1hA.y},{b1hA.z,b1hA.w},{b1hB.x,b1hB.y},{b1hB.z,b1hB.w}};
            u32 b1l[4][2] = {{b1lA.x,b1lA.y},{b1lA.z,b1lA.w},{b1lB.x,b1lB.y},{b1lB.z,b1lB.w}};
            u32 bgh[4][2] = {{bghA.x,bghA.y},{bghA.z,bghA.w},{bghB.x,bghB.y},{bghB.z,bghB.w}};
            u32 bgl[4][2] = {{bglA.x,bglA.y},{bglA.z,bglA.w},{bglB.x,bglB.y},{bglB.z,bglB.w}};
#pragma unroll
            for (int i = 0; i < 2; ++i) {
#pragma unroll
                for (int j = 0; j < 4; ++j) {
                    mma16816(acc1[i][j], ahf[i].x, ahf[i].y, ahf[i].z, ahf[i].w, b1h[j][0], b1h[j][1]);
                    mma16816(acc1[i][j], ahf[i].x, ahf[i].y, ahf[i].z, ahf[i].w, b1l[j][0], b1l[j][1]);
                    mma16816(acc1[i][j], alf[i].x, alf[i].y, alf[i].z, alf[i].w, b1h[j][0], b1h[j][1]);
                    mma16816(accg[i][j], ahf[i].x, ahf[i].y, ahf[i].z, ahf[i].w, bgh[j][0], bgh[j][1]);
                    mma16816(accg[i][j], ahf[i].x, ahf[i].y, ahf[i].z, ahf[i].w, bgl[j][0], bgl[j][1]);
                    mma16816(accg[i][j], alf[i].x, alf[i].y, alf[i].z, alf[i].w, bgh[j][0], bgh[j][1]);
                }
            }
        }
        __syncthreads();
        if (c + 2 < NCH_CHUNKS) issue(c + 2, (c + 2) % 3);
        CP_COMMIT();
    }

    // epilogue: gate, split, write pass2 A-fragment images directly
#pragma unroll
    for (int i = 0; i < 2; ++i) {
        int mt = wm * 2 + i;
#pragma unroll
        for (int g = 0; g < 2; ++g) {
            float hv[8];
#pragma unroll
            for (int k = 0; k < 4; ++k) {
                hv[k]     = acc1[i][2*g][k]   * (1.f / (1.f + __expf(-accg[i][2*g][k])));
                hv[4 + k] = acc1[i][2*g+1][k] * (1.f / (1.f + __expf(-accg[i][2*g+1][k])));
            }
            uint4 hi, lo;
            split2(hv[0], hv[1], hi.x, lo.x);
            split2(hv[2], hv[3], hi.y, lo.y);
            split2(hv[4], hv[5], hi.z, lo.z);
            split2(hv[6], hv[7], hi.w, lo.w);
            int ksp = nch * 4 + wn * 2 + g;
            size_t off = ((size_t)tile * 96 + ksp) * 256 + mt * 32 + lane;
            g_hFh[off] = hi;
            g_hFl[off] = lo;
        }
    }
}

// ---------------- pass 2: y = h @ W2 ----------------
// CTA: 256 thr = 8 warps (2M x 4N). M=128, N=128. K chunk 32, 48 chunks.
__global__ void __launch_bounds__(256) pass2_mma(void) {
    int tile = blockIdx.y;
    if (tile >= g_ntiles) return;
    int nc = blockIdx.x;                   // 0..5 (128 D-cols each)
    int e = g_tile_e[tile];
    extern __shared__ char dsm[];
    u32 sbase = smem_u32(dsm);

    int tid = threadIdx.x;
    int wid = tid >> 5, lane = tid & 31;
    int wm = wid >> 2, wn = wid & 3;

    const uint4* Ah = g_hFh + (size_t)tile * (96 * 8 * 32);
    const uint4* Al = g_hFl + (size_t)tile * (96 * 8 * 32);
    size_t eb = (size_t)e * (96 * 24 * 32 * 4);
    const uint2* Bh = g_w2Fh + eb;
    const uint2* Bl = g_w2Fl + eb;

    auto issue = [&](int c, int slot) {
        u32 st = sbase + slot * STAGE_BYTES;
        const uint4* ah = Ah + (size_t)c * 512;
        const uint4* al = Al + (size_t)c * 512;
        cp16(st + tid * 16,                 ah + tid);
        cp16(st + (tid + 256) * 16,         ah + tid + 256);
        cp16(st + 8192 + tid * 16,          al + tid);
        cp16(st + 8192 + (tid + 256) * 16,  al + tid + 256);
#pragma unroll
        for (int r = 0; r < 2; ++r) {
            int idx = tid + r * 256;
            int ksl = idx >> 8, rem = idx & 255;
            int ngl = rem >> 6, lane2 = (rem & 63) >> 1, half = rem & 1;
            size_t bsrc = (((size_t)(2 * c + ksl) * 24 + nc * 4 + ngl) * 32 + lane2) * 4 + half * 2;
            u32 bdst = ((ksl * 4 + ngl) * 32 + lane2) * 32 + half * 16;
            cp16(st + 16384 + bdst, Bh + bsrc);
            cp16(st + 24576 + bdst, Bl + bsrc);
        }
    };

    float acc[4][4][4];
#pragma unroll
    for (int i = 0; i < 4; ++i)
#pragma unroll
        for (int j = 0; j < 4; ++j)
#pragma unroll
            for (int k = 0; k < 4; ++k) acc[i][j][k] = 0.f;

    issue(0, 0); CP_COMMIT();
    issue(1, 1); CP_COMMIT();

    const int NCH_CHUNKS = 48;
    for (int c = 0; c < NCH_CHUNKS; ++c) {
        CP_WAIT1();
        __syncthreads();
        int slot = c % 3;
        const char* st = dsm + slot * STAGE_BYTES;
#pragma unroll
        for (int ksl = 0; ksl < 2; ++ksl) {
            u32 bo = ((ksl * 4 + wn) * 32 + lane) * 32;
            uint4 bhA = *(const uint4*)(st + 16384 + bo);
            uint4 bhB = *(const uint4*)(st + 16384 + bo + 16);
            uint4 blA = *(const uint4*)(st + 24576 + bo);
            uint4 blB = *(const uint4*)(st + 24576 + bo + 16);
            u32 bh[4][2] = {{bhA.x,bhA.y},{bhA.z,bhA.w},{bhB.x,bhB.y},{bhB.z,bhB.w}};
            u32 bl[4][2] = {{blA.x,blA.y},{blA.z,blA.w},{blB.x,blB.y},{blB.z,blB.w}};
#pragma unroll
            for (int i = 0; i < 4; ++i) {
                int mt = wm * 4 + i;
                u32 ao = ((ksl * 8 + mt) * 32 + lane) * 16;
                uint4 ah = *(const uint4*)(st + ao);
                uint4 al = *(const uint4*)(st + 8192 + ao);
#pragma unroll
                for (int j = 0; j < 4; ++j) {
                    mma16816(acc[i][j], ah.x, ah.y, ah.z, ah.w, bh[j][0], bh[j][1]);
                    mma16816(acc[i][j], ah.x, ah.y, ah.z, ah.w, bl[j][0], bl[j][1]);
                    mma16816(acc[i][j], al.x, al.y, al.z, al.w, bh[j][0], bh[j][1]);
                }
            }
        }
        __syncthreads();
        if (c + 2 < NCH_CHUNKS) issue(c + 2, (c + 2) % 3);
        CP_COMMIT();
    }

    // epilogue: write y fp32
    int rbase = (lane >> 2);
    int cbase = nc * 128 + wn * 32 + (lane & 3) * 2;
#pragma unroll
    for (int i = 0; i < 4; ++i) {
        int mt = wm * 4 + i;
#pragma unroll
        for (int j = 0; j < 4; ++j) {
            int col = cbase + j * 8;
            int row0 = mt * 16 + rbase;
            float* y0 = g_y + ((size_t)tile * 128 + row0) * D_DIM + col;
            float* y1 = y0 + 8 * D_DIM;
            *(float2*)y0 = make_float2(acc[i][j][0], acc[i][j][1]);
            *(float2*)y1 = make_float2(acc[i][j][2], acc[i][j][3]);
        }
    }
}

// ---------------- combine ----------------
__global__ void __launch_bounds__(192) combine_kernel(float* __restrict__ out) {
    int t = blockIdx.x;
    int d = threadIdx.x;
    float w0 = g_tw[2*t], w1 = g_tw[2*t+1];
    const float4* y0 = (const float4*)(g_y + (size_t)g_pos[2*t]   * D_DIM);
    const float4* y1 = (const float4*)(g_y + (size_t)g_pos[2*t+1] * D_DIM);
    float4 a = y0[d], b = y1[d], o;
    o.x = w0 * a.x + w1 * b.x;
    o.y = w0 * a.y + w1 * b.y;
    o.z = w0 * a.z + w1 * b.z;
    o.w = w0 * a.w + w1 * b.w;
    ((float4*)(out + (size_t)t * D_DIM))[d] = o;
}

// ---------------- launch ----------------
extern "C" void kernel_launch(void* const* d_in, const int* in_sizes, int n_in,
                              void* d_out, int out_size) {
    const float* X      = (const float*)d_in[0];
    const float* scores = (const float*)d_in[1];
    const float* W1     = (const float*)d_in[2];
    const float* Wg     = (const float*)d_in[3];
    const float* W2     = (const float*)d_in[4];
    float* out = (float*)d_out;

    int ntok = in_sizes[0] / D_DIM;

    cudaFuncSetAttribute(pass1_mma, cudaFuncAttributeMaxDynamicSharedMemorySize, SMEM_DYN);
    cudaFuncSetAttribute(pass2_mma, cudaFuncAttributeMaxDynamicSharedMemorySize, SMEM_DYN);

    zero_meta_kernel<<<1, 32>>>();
    fill_tok_kernel<<<(PS_MAX + 1023) / 1024, 1024>>>();
    route_kernel<<<(ntok + 255) / 256, 256>>>(scores, ntok);
    scan_kernel<<<1, 32>>>();
    scatter_kernel<<<(ntok + 255) / 256, 256>>>(ntok);

    gather_a_kernel<<<MAXTILES, 256>>>(X);
    conv_w_kernel<<<dim3(48, 12, E_NUM), 256>>>(W1, 0, D_DIM, H_DIM);
    conv_w_kernel<<<dim3(48, 12, E_NUM), 256>>>(Wg, 1, D_DIM, H_DIM);
    conv_w_kernel<<<dim3(96, 6, E_NUM), 256>>>(W2, 2, H_DIM, D_DIM);

    pass1_mma<<<dim3(24, MAXTILES), 256, SMEM_DYN>>>();
    pass2_mma<<<dim3(6, MAXTILES), 256, SMEM_DYN>>>();

    combine_kernel<<<ntok, 192>>>(out);
}